// round 5
// baseline (speedup 1.0000x reference)
#include <cuda_runtime.h>
#include <cstdint>

// MLP: x[N,16] -> L1(16->32)+BN+ReLU -> L2(32->32)+BN+ReLU -> L3(32->32)+BN+ReLU -> L4(32->1)
// v3: 2 rows/thread (256-row tiles), conflict-free stride-33 smem, coalesced z stores
// via smem re-staging, BN coeffs in registers, packed f32x2 FFMA throughout.

#define EPSV 1e-5f
#define GRID_MAIN 1024
#define TILE_ROWS 256
#define KP 33                         // smem row stride (floats): bank = (r + c) % 32, conflict-free

__device__ float g_Z[(size_t)2097152 * 32];
__device__ float g_partial[GRID_MAIN * 64];
__device__ float g_bnab[64];          // a[32], c[32]

// ---------------- packed f32x2 helpers ----------------
__device__ __forceinline__ unsigned long long pack2(float lo, float hi) {
    unsigned long long r;
    asm("mov.b64 %0, {%1, %2};" : "=l"(r) : "r"(__float_as_uint(lo)), "r"(__float_as_uint(hi)));
    return r;
}
__device__ __forceinline__ void unpack2(unsigned long long v, float& lo, float& hi) {
    unsigned int a, b;
    asm("mov.b64 {%0, %1}, %2;" : "=r"(a), "=r"(b) : "l"(v));
    lo = __uint_as_float(a); hi = __uint_as_float(b);
}
__device__ __forceinline__ unsigned long long splat2(float x) {
    unsigned long long r;
    unsigned int xi = __float_as_uint(x);
    asm("mov.b64 %0, {%1, %1};" : "=l"(r) : "r"(xi));
    return r;
}
__device__ __forceinline__ void fma2(unsigned long long& d, unsigned long long a, unsigned long long b) {
    asm("fma.rn.f32x2 %0, %1, %2, %0;" : "+l"(d) : "l"(a), "l"(b));
}
__device__ __forceinline__ void add2(unsigned long long& d, unsigned long long a) {
    asm("add.rn.f32x2 %0, %0, %1;" : "+l"(d) : "l"(a));
}

// ---------------- layer kernel (KIN -> 32) ----------------
// 256 threads. Tile = 256 rows. half = tid>>7 selects features [16h,16h+16);
// each thread computes its 16 features for rows r=tid&127 and r+128.
template<int KIN, bool BN>
__global__ void __launch_bounds__(256, 2) layer_kernel(
    const float* __restrict__ xin,
    const float* __restrict__ W,      // [32, KIN] row-major
    const float* __restrict__ b,      // [32]
    int tpc)
{
    __shared__ float sTile[TILE_ROWS * KP];          // input tile, then reused for z staging
    __shared__ unsigned long long sWp[KIN * 16];     // sWp[k*16+jj] = {W[2jj][k], W[2jj+1][k]}
    __shared__ unsigned long long sBp[16];
    __shared__ unsigned long long sRed[8][16];

    const int tid = threadIdx.x;

    for (int idx = tid; idx < KIN * 16; idx += 256) {
        int k = idx >> 4, jj = idx & 15;
        sWp[idx] = pack2(W[(2 * jj) * KIN + k], W[(2 * jj + 1) * KIN + k]);
    }
    if (tid < 16) sBp[tid] = pack2(b[2 * tid], b[2 * tid + 1]);

    // BN coefficients of the INPUT layer, registered per thread's staging columns
    float aR[4], cR[4];
    if (BN) {
        const int c0 = (tid % (KIN / 4)) * 4;        // invariant across this thread's chunks
#pragma unroll
        for (int u = 0; u < 4; ++u) { aR[u] = g_bnab[c0 + u]; cR[u] = g_bnab[32 + c0 + u]; }
    }

    const int half = tid >> 7;
    const int r    = tid & 127;

    unsigned long long vsum[8], vsq[8];
#pragma unroll
    for (int m = 0; m < 8; ++m) { vsum[m] = 0ull; vsq[m] = 0ull; }

    const float* zin = BN ? (const float*)g_Z : xin;
    constexpr int PER_IN  = (TILE_ROWS * KIN / 4) / 256;   // f4 loads per thread
    constexpr int KIN4 = KIN / 4;

    for (int t = 0; t < tpc; ++t) {
        const size_t row0 = ((size_t)blockIdx.x * tpc + t) * TILE_ROWS;

        // ---- stage input tile (coalesced LDG.128), BN+ReLU applied in flight ----
        const float4* src = reinterpret_cast<const float4*>(zin + row0 * KIN);
#pragma unroll
        for (int j = 0; j < PER_IN; ++j) {
            int i = tid + 256 * j;
            float4 v = src[i];
            int rw = i / KIN4;
            int c  = (i % KIN4) * 4;
            if (BN) {
                v.x = fmaxf(fmaf(v.x, aR[0], cR[0]), 0.0f);
                v.y = fmaxf(fmaf(v.y, aR[1], cR[1]), 0.0f);
                v.z = fmaxf(fmaf(v.z, aR[2], cR[2]), 0.0f);
                v.w = fmaxf(fmaf(v.w, aR[3], cR[3]), 0.0f);
            }
            float* d = &sTile[rw * KP + c];
            d[0] = v.x; d[1] = v.y; d[2] = v.z; d[3] = v.w;
        }
        __syncthreads();

        // ---- GEMM: 16 features x 2 rows per thread ----
        unsigned long long z0[8], z1[8];
        const unsigned long long* bp = &sBp[half * 8];
#pragma unroll
        for (int m = 0; m < 8; ++m) { z0[m] = bp[m]; z1[m] = bp[m]; }

#pragma unroll
        for (int k = 0; k < KIN; ++k) {
            unsigned long long p0 = splat2(sTile[r * KP + k]);
            unsigned long long p1 = splat2(sTile[(r + 128) * KP + k]);
            const ulonglong2* wp = reinterpret_cast<const ulonglong2*>(&sWp[k * 16 + half * 8]);
            ulonglong2 wa = wp[0], wb = wp[1], wc = wp[2], wd = wp[3];
            fma2(z0[0], p0, wa.x); fma2(z1[0], p1, wa.x);
            fma2(z0[1], p0, wa.y); fma2(z1[1], p1, wa.y);
            fma2(z0[2], p0, wb.x); fma2(z1[2], p1, wb.x);
            fma2(z0[3], p0, wb.y); fma2(z1[3], p1, wb.y);
            fma2(z0[4], p0, wc.x); fma2(z1[4], p1, wc.x);
            fma2(z0[5], p0, wc.y); fma2(z1[5], p1, wc.y);
            fma2(z0[6], p0, wd.x); fma2(z1[6], p1, wd.x);
            fma2(z0[7], p0, wd.y); fma2(z1[7], p1, wd.y);
        }

        // ---- stats (both rows into shared accumulators) ----
#pragma unroll
        for (int m = 0; m < 8; ++m) {
            add2(vsum[m], z0[m]); add2(vsum[m], z1[m]);
            fma2(vsq[m], z0[m], z0[m]); fma2(vsq[m], z1[m], z1[m]);
        }
        __syncthreads();

        // ---- scatter z into sTile (conflict-free scalar STS) ----
#pragma unroll
        for (int m = 0; m < 8; ++m) {
            float f0, f1;
            unpack2(z0[m], f0, f1);
            sTile[r * KP + half * 16 + 2 * m]     = f0;
            sTile[r * KP + half * 16 + 2 * m + 1] = f1;
            unpack2(z1[m], f0, f1);
            sTile[(r + 128) * KP + half * 16 + 2 * m]     = f0;
            sTile[(r + 128) * KP + half * 16 + 2 * m + 1] = f1;
        }
        __syncthreads();

        // ---- coalesced z store: linear float4 over the tile ----
        float4* dst = reinterpret_cast<float4*>(g_Z + row0 * 32);
#pragma unroll
        for (int j = 0; j < 8; ++j) {
            int i = tid + 256 * j;
            int rw = i >> 3, c = (i & 7) * 4;
            const float* s = &sTile[rw * KP + c];
            float4 v; v.x = s[0]; v.y = s[1]; v.z = s[2]; v.w = s[3];
            dst[i] = v;
        }
        __syncthreads();   // before next tile's staging overwrites sTile
    }

    // ---- deterministic stat reduction ----
#pragma unroll
    for (int off = 16; off > 0; off >>= 1) {
#pragma unroll
        for (int m = 0; m < 8; ++m) {
            add2(vsum[m], __shfl_xor_sync(0xffffffffu, vsum[m], off));
            add2(vsq[m],  __shfl_xor_sync(0xffffffffu, vsq[m],  off));
        }
    }
    const int w = tid >> 5, lane = tid & 31;
    if (lane == 0) {
#pragma unroll
        for (int m = 0; m < 8; ++m) { sRed[w][m] = vsum[m]; sRed[w][8 + m] = vsq[m]; }
    }
    __syncthreads();
    if (tid < 64) {
        int s = tid >> 5, j = tid & 31;
        int hh = j >> 4, m = (j & 15) >> 1, hi = j & 1;
        float tot = 0.0f;
        for (int w2 = hh * 4; w2 < hh * 4 + 4; ++w2) {
            float lo, hp; unpack2(sRed[w2][s * 8 + m], lo, hp);
            tot += hi ? hp : lo;
        }
        g_partial[blockIdx.x * 64 + tid] = tot;
    }
}

// ---------------- stat reduce + BN coefficient kernel ----------------
__global__ void reduce_kernel(const float* __restrict__ gamma,
                              const float* __restrict__ beta,
                              float invN, int nPart)
{
    __shared__ float sred[16][64];
    __shared__ float stot[64];
    const int tid = threadIdx.x;          // 1024 threads
    const int f = tid & 63, chunk = tid >> 6;
    const int per = nPart >> 4;           // 64
    const int c0 = chunk * per;
    float s0 = 0.f, s1 = 0.f, s2 = 0.f, s3 = 0.f;
    for (int c = c0; c < c0 + per; c += 4) {
        s0 += g_partial[(c + 0) * 64 + f];
        s1 += g_partial[(c + 1) * 64 + f];
        s2 += g_partial[(c + 2) * 64 + f];
        s3 += g_partial[(c + 3) * 64 + f];
    }
    sred[chunk][f] = (s0 + s1) + (s2 + s3);
    __syncthreads();
    if (tid < 64) {
        float t = 0.0f;
#pragma unroll
        for (int ch = 0; ch < 16; ++ch) t += sred[ch][tid];
        stot[tid] = t;
    }
    __syncthreads();
    if (tid < 32) {
        float mean = stot[tid] * invN;
        float var  = stot[32 + tid] * invN - mean * mean;
        float a = gamma[tid] * rsqrtf(var + EPSV);
        g_bnab[tid]      = a;
        g_bnab[32 + tid] = beta[tid] - mean * a;
    }
}

// ---------------- final kernel: BN3+ReLU then 32->1 dot ----------------
__global__ void __launch_bounds__(256) final_kernel(
    const float* __restrict__ W4, const float* __restrict__ b4,
    float* __restrict__ out)
{
    __shared__ float sA[32], sC[32], sW[32];
    const int tid = threadIdx.x;
    if (tid < 32) { sA[tid] = g_bnab[tid]; sC[tid] = g_bnab[32 + tid]; sW[tid] = W4[tid]; }
    __syncthreads();
    const size_t row = (size_t)blockIdx.x * 256 + tid;
    const float4* zr = reinterpret_cast<const float4*>(g_Z + row * 32);
    float acc = b4[0];
#pragma unroll
    for (int i = 0; i < 8; ++i) {
        float4 v = zr[i];
        int k = i * 4;
        acc = fmaf(fmaxf(fmaf(v.x, sA[k + 0], sC[k + 0]), 0.0f), sW[k + 0], acc);
        acc = fmaf(fmaxf(fmaf(v.y, sA[k + 1], sC[k + 1]), 0.0f), sW[k + 1], acc);
        acc = fmaf(fmaxf(fmaf(v.z, sA[k + 2], sC[k + 2]), 0.0f), sW[k + 2], acc);
        acc = fmaf(fmaxf(fmaf(v.w, sA[k + 3], sC[k + 3]), 0.0f), sW[k + 3], acc);
    }
    out[row] = acc;
}

// Dummy kernel: shifts the ncu capture window (-s 5 -c 1) onto layer_kernel L3.
__global__ void dummy_kernel() {}

// ---------------- launcher ----------------
extern "C" void kernel_launch(void* const* d_in, const int* in_sizes, int n_in,
                              void* d_out, int out_size)
{
    const float* x   = (const float*)d_in[0];
    const float* W1  = (const float*)d_in[1];
    const float* b1  = (const float*)d_in[2];
    const float* g1  = (const float*)d_in[3];
    const float* be1 = (const float*)d_in[4];
    const float* W2  = (const float*)d_in[5];
    const float* b2  = (const float*)d_in[6];
    const float* g2  = (const float*)d_in[7];
    const float* be2 = (const float*)d_in[8];
    const float* W3  = (const float*)d_in[9];
    const float* b3  = (const float*)d_in[10];
    const float* g3  = (const float*)d_in[11];
    const float* be3 = (const float*)d_in[12];
    const float* W4  = (const float*)d_in[13];
    const float* b4  = (const float*)d_in[14];

    const int n   = in_sizes[0] / 16;                       // 2097152 rows
    const int tpc = n / (GRID_MAIN * TILE_ROWS);            // 8
    const float invN = 1.0f / (float)n;

    layer_kernel<16, false><<<GRID_MAIN, 256>>>(x, W1, b1, tpc);   // launch 0
    reduce_kernel<<<1, 1024>>>(g1, be1, invN, GRID_MAIN);          // launch 1

    layer_kernel<32, true><<<GRID_MAIN, 256>>>(x, W2, b2, tpc);    // launch 2
    reduce_kernel<<<1, 1024>>>(g2, be2, invN, GRID_MAIN);          // launch 3

    dummy_kernel<<<1, 1>>>();                                      // launch 4 (ncu alignment)

    layer_kernel<32, true><<<GRID_MAIN, 256>>>(x, W3, b3, tpc);    // launch 5 <- profiled
    reduce_kernel<<<1, 1024>>>(g3, be3, invN, GRID_MAIN);          // launch 6

    final_kernel<<<n / 256, 256>>>(W4, b4, (float*)d_out);         // launch 7
}

// round 6
// speedup vs baseline: 1.5565x; 1.5565x over previous
#include <cuda_runtime.h>
#include <cstdint>

// MLP: x[N,16] -> L1(16->32)+BN+ReLU -> L2(32->32)+BN+ReLU -> L3(32->32)+BN+ReLU -> L4(32->1)
// v3: 2 rows/thread (256-row tiles), conflict-free stride-33 smem, coalesced z stores
// via smem re-staging, BN coeffs in registers, packed f32x2 FFMA throughout.

#define EPSV 1e-5f
#define GRID_MAIN 1024
#define TILE_ROWS 256
#define KP 33                         // smem row stride (floats): bank = (r + c) % 32, conflict-free

__device__ float g_Z[(size_t)2097152 * 32];
__device__ float g_partial[GRID_MAIN * 64];
__device__ float g_bnab[64];          // a[32], c[32]

// ---------------- packed f32x2 helpers ----------------
__device__ __forceinline__ unsigned long long pack2(float lo, float hi) {
    unsigned long long r;
    asm("mov.b64 %0, {%1, %2};" : "=l"(r) : "r"(__float_as_uint(lo)), "r"(__float_as_uint(hi)));
    return r;
}
__device__ __forceinline__ void unpack2(unsigned long long v, float& lo, float& hi) {
    unsigned int a, b;
    asm("mov.b64 {%0, %1}, %2;" : "=r"(a), "=r"(b) : "l"(v));
    lo = __uint_as_float(a); hi = __uint_as_float(b);
}
__device__ __forceinline__ unsigned long long splat2(float x) {
    unsigned long long r;
    unsigned int xi = __float_as_uint(x);
    asm("mov.b64 %0, {%1, %1};" : "=l"(r) : "r"(xi));
    return r;
}
__device__ __forceinline__ void fma2(unsigned long long& d, unsigned long long a, unsigned long long b) {
    asm("fma.rn.f32x2 %0, %1, %2, %0;" : "+l"(d) : "l"(a), "l"(b));
}
__device__ __forceinline__ void add2(unsigned long long& d, unsigned long long a) {
    asm("add.rn.f32x2 %0, %0, %1;" : "+l"(d) : "l"(a));
}

// ---------------- layer kernel (KIN -> 32) ----------------
// 256 threads. Tile = 256 rows. half = tid>>7 selects features [16h,16h+16);
// each thread computes its 16 features for rows r=tid&127 and r+128.
template<int KIN, bool BN>
__global__ void __launch_bounds__(256, 2) layer_kernel(
    const float* __restrict__ xin,
    const float* __restrict__ W,      // [32, KIN] row-major
    const float* __restrict__ b,      // [32]
    int tpc)
{
    __shared__ float sTile[TILE_ROWS * KP];          // input tile, then reused for z staging
    __shared__ unsigned long long sWp[KIN * 16];     // sWp[k*16+jj] = {W[2jj][k], W[2jj+1][k]}
    __shared__ unsigned long long sBp[16];
    __shared__ unsigned long long sRed[8][16];

    const int tid = threadIdx.x;

    for (int idx = tid; idx < KIN * 16; idx += 256) {
        int k = idx >> 4, jj = idx & 15;
        sWp[idx] = pack2(W[(2 * jj) * KIN + k], W[(2 * jj + 1) * KIN + k]);
    }
    if (tid < 16) sBp[tid] = pack2(b[2 * tid], b[2 * tid + 1]);

    // BN coefficients of the INPUT layer, registered per thread's staging columns
    float aR[4], cR[4];
    if (BN) {
        const int c0 = (tid % (KIN / 4)) * 4;        // invariant across this thread's chunks
#pragma unroll
        for (int u = 0; u < 4; ++u) { aR[u] = g_bnab[c0 + u]; cR[u] = g_bnab[32 + c0 + u]; }
    }

    const int half = tid >> 7;
    const int r    = tid & 127;

    unsigned long long vsum[8], vsq[8];
#pragma unroll
    for (int m = 0; m < 8; ++m) { vsum[m] = 0ull; vsq[m] = 0ull; }

    const float* zin = BN ? (const float*)g_Z : xin;
    constexpr int PER_IN  = (TILE_ROWS * KIN / 4) / 256;   // f4 loads per thread
    constexpr int KIN4 = KIN / 4;

    for (int t = 0; t < tpc; ++t) {
        const size_t row0 = ((size_t)blockIdx.x * tpc + t) * TILE_ROWS;

        // ---- stage input tile (coalesced LDG.128), BN+ReLU applied in flight ----
        const float4* src = reinterpret_cast<const float4*>(zin + row0 * KIN);
#pragma unroll
        for (int j = 0; j < PER_IN; ++j) {
            int i = tid + 256 * j;
            float4 v = src[i];
            int rw = i / KIN4;
            int c  = (i % KIN4) * 4;
            if (BN) {
                v.x = fmaxf(fmaf(v.x, aR[0], cR[0]), 0.0f);
                v.y = fmaxf(fmaf(v.y, aR[1], cR[1]), 0.0f);
                v.z = fmaxf(fmaf(v.z, aR[2], cR[2]), 0.0f);
                v.w = fmaxf(fmaf(v.w, aR[3], cR[3]), 0.0f);
            }
            float* d = &sTile[rw * KP + c];
            d[0] = v.x; d[1] = v.y; d[2] = v.z; d[3] = v.w;
        }
        __syncthreads();

        // ---- GEMM: 16 features x 2 rows per thread ----
        unsigned long long z0[8], z1[8];
        const unsigned long long* bp = &sBp[half * 8];
#pragma unroll
        for (int m = 0; m < 8; ++m) { z0[m] = bp[m]; z1[m] = bp[m]; }

#pragma unroll
        for (int k = 0; k < KIN; ++k) {
            unsigned long long p0 = splat2(sTile[r * KP + k]);
            unsigned long long p1 = splat2(sTile[(r + 128) * KP + k]);
            const ulonglong2* wp = reinterpret_cast<const ulonglong2*>(&sWp[k * 16 + half * 8]);
            ulonglong2 wa = wp[0], wb = wp[1], wc = wp[2], wd = wp[3];
            fma2(z0[0], p0, wa.x); fma2(z1[0], p1, wa.x);
            fma2(z0[1], p0, wa.y); fma2(z1[1], p1, wa.y);
            fma2(z0[2], p0, wb.x); fma2(z1[2], p1, wb.x);
            fma2(z0[3], p0, wb.y); fma2(z1[3], p1, wb.y);
            fma2(z0[4], p0, wc.x); fma2(z1[4], p1, wc.x);
            fma2(z0[5], p0, wc.y); fma2(z1[5], p1, wc.y);
            fma2(z0[6], p0, wd.x); fma2(z1[6], p1, wd.x);
            fma2(z0[7], p0, wd.y); fma2(z1[7], p1, wd.y);
        }

        // ---- stats (both rows into shared accumulators) ----
#pragma unroll
        for (int m = 0; m < 8; ++m) {
            add2(vsum[m], z0[m]); add2(vsum[m], z1[m]);
            fma2(vsq[m], z0[m], z0[m]); fma2(vsq[m], z1[m], z1[m]);
        }
        __syncthreads();

        // ---- scatter z into sTile (conflict-free scalar STS) ----
#pragma unroll
        for (int m = 0; m < 8; ++m) {
            float f0, f1;
            unpack2(z0[m], f0, f1);
            sTile[r * KP + half * 16 + 2 * m]     = f0;
            sTile[r * KP + half * 16 + 2 * m + 1] = f1;
            unpack2(z1[m], f0, f1);
            sTile[(r + 128) * KP + half * 16 + 2 * m]     = f0;
            sTile[(r + 128) * KP + half * 16 + 2 * m + 1] = f1;
        }
        __syncthreads();

        // ---- coalesced z store: linear float4 over the tile ----
        float4* dst = reinterpret_cast<float4*>(g_Z + row0 * 32);
#pragma unroll
        for (int j = 0; j < 8; ++j) {
            int i = tid + 256 * j;
            int rw = i >> 3, c = (i & 7) * 4;
            const float* s = &sTile[rw * KP + c];
            float4 v; v.x = s[0]; v.y = s[1]; v.z = s[2]; v.w = s[3];
            dst[i] = v;
        }
        __syncthreads();   // before next tile's staging overwrites sTile
    }

    // ---- deterministic stat reduction ----
#pragma unroll
    for (int off = 16; off > 0; off >>= 1) {
#pragma unroll
        for (int m = 0; m < 8; ++m) {
            add2(vsum[m], __shfl_xor_sync(0xffffffffu, vsum[m], off));
            add2(vsq[m],  __shfl_xor_sync(0xffffffffu, vsq[m],  off));
        }
    }
    const int w = tid >> 5, lane = tid & 31;
    if (lane == 0) {
#pragma unroll
        for (int m = 0; m < 8; ++m) { sRed[w][m] = vsum[m]; sRed[w][8 + m] = vsq[m]; }
    }
    __syncthreads();
    if (tid < 64) {
        int s = tid >> 5, j = tid & 31;
        int hh = j >> 4, m = (j & 15) >> 1, hi = j & 1;
        float tot = 0.0f;
        for (int w2 = hh * 4; w2 < hh * 4 + 4; ++w2) {
            float lo, hp; unpack2(sRed[w2][s * 8 + m], lo, hp);
            tot += hi ? hp : lo;
        }
        g_partial[blockIdx.x * 64 + tid] = tot;
    }
}

// ---------------- stat reduce + BN coefficient kernel ----------------
__global__ void reduce_kernel(const float* __restrict__ gamma,
                              const float* __restrict__ beta,
                              float invN, int nPart)
{
    __shared__ float sred[16][64];
    __shared__ float stot[64];
    const int tid = threadIdx.x;          // 1024 threads
    const int f = tid & 63, chunk = tid >> 6;
    const int per = nPart >> 4;           // 64
    const int c0 = chunk * per;
    float s0 = 0.f, s1 = 0.f, s2 = 0.f, s3 = 0.f;
    for (int c = c0; c < c0 + per; c += 4) {
        s0 += g_partial[(c + 0) * 64 + f];
        s1 += g_partial[(c + 1) * 64 + f];
        s2 += g_partial[(c + 2) * 64 + f];
        s3 += g_partial[(c + 3) * 64 + f];
    }
    sred[chunk][f] = (s0 + s1) + (s2 + s3);
    __syncthreads();
    if (tid < 64) {
        float t = 0.0f;
#pragma unroll
        for (int ch = 0; ch < 16; ++ch) t += sred[ch][tid];
        stot[tid] = t;
    }
    __syncthreads();
    if (tid < 32) {
        float mean = stot[tid] * invN;
        float var  = stot[32 + tid] * invN - mean * mean;
        float a = gamma[tid] * rsqrtf(var + EPSV);
        g_bnab[tid]      = a;
        g_bnab[32 + tid] = beta[tid] - mean * a;
    }
}

// ---------------- final kernel: BN3+ReLU then 32->1 dot ----------------
__global__ void __launch_bounds__(256) final_kernel(
    const float* __restrict__ W4, const float* __restrict__ b4,
    float* __restrict__ out)
{
    __shared__ float sA[32], sC[32], sW[32];
    const int tid = threadIdx.x;
    if (tid < 32) { sA[tid] = g_bnab[tid]; sC[tid] = g_bnab[32 + tid]; sW[tid] = W4[tid]; }
    __syncthreads();
    const size_t row = (size_t)blockIdx.x * 256 + tid;
    const float4* zr = reinterpret_cast<const float4*>(g_Z + row * 32);
    float acc = b4[0];
#pragma unroll
    for (int i = 0; i < 8; ++i) {
        float4 v = zr[i];
        int k = i * 4;
        acc = fmaf(fmaxf(fmaf(v.x, sA[k + 0], sC[k + 0]), 0.0f), sW[k + 0], acc);
        acc = fmaf(fmaxf(fmaf(v.y, sA[k + 1], sC[k + 1]), 0.0f), sW[k + 1], acc);
        acc = fmaf(fmaxf(fmaf(v.z, sA[k + 2], sC[k + 2]), 0.0f), sW[k + 2], acc);
        acc = fmaf(fmaxf(fmaf(v.w, sA[k + 3], sC[k + 3]), 0.0f), sW[k + 3], acc);
    }
    out[row] = acc;
}

// Dummy kernel: shifts the ncu capture window (-s 5 -c 1) onto layer_kernel L3.
__global__ void dummy_kernel() {}

// ---------------- launcher ----------------
extern "C" void kernel_launch(void* const* d_in, const int* in_sizes, int n_in,
                              void* d_out, int out_size)
{
    const float* x   = (const float*)d_in[0];
    const float* W1  = (const float*)d_in[1];
    const float* b1  = (const float*)d_in[2];
    const float* g1  = (const float*)d_in[3];
    const float* be1 = (const float*)d_in[4];
    const float* W2  = (const float*)d_in[5];
    const float* b2  = (const float*)d_in[6];
    const float* g2  = (const float*)d_in[7];
    const float* be2 = (const float*)d_in[8];
    const float* W3  = (const float*)d_in[9];
    const float* b3  = (const float*)d_in[10];
    const float* g3  = (const float*)d_in[11];
    const float* be3 = (const float*)d_in[12];
    const float* W4  = (const float*)d_in[13];
    const float* b4  = (const float*)d_in[14];

    const int n   = in_sizes[0] / 16;                       // 2097152 rows
    const int tpc = n / (GRID_MAIN * TILE_ROWS);            // 8
    const float invN = 1.0f / (float)n;

    layer_kernel<16, false><<<GRID_MAIN, 256>>>(x, W1, b1, tpc);   // launch 0
    reduce_kernel<<<1, 1024>>>(g1, be1, invN, GRID_MAIN);          // launch 1

    layer_kernel<32, true><<<GRID_MAIN, 256>>>(x, W2, b2, tpc);    // launch 2
    reduce_kernel<<<1, 1024>>>(g2, be2, invN, GRID_MAIN);          // launch 3

    dummy_kernel<<<1, 1>>>();                                      // launch 4 (ncu alignment)

    layer_kernel<32, true><<<GRID_MAIN, 256>>>(x, W3, b3, tpc);    // launch 5 <- profiled
    reduce_kernel<<<1, 1024>>>(g3, be3, invN, GRID_MAIN);          // launch 6

    final_kernel<<<n / 256, 256>>>(W4, b4, (float*)d_out);         // launch 7
}